// round 16
// baseline (speedup 1.0000x reference)
#include <cuda_runtime.h>
#include <cuda_bf16.h>
#include <cuda_fp16.h>
#include <cstdint>

// Problem constants
#define BB   4
#define NTOK 4096
#define PD   1024
#define DD   16
#define NC   (NTOK / DD)
#define GK   1024                 // K of both GEMMs
#define GM   (BB * NTOK)          // 16384 rows

// ---------------------------------------------------------------------------
// Scratch (device globals: allocation-free rule)
// ---------------------------------------------------------------------------
__device__ __half g_P[(size_t)GM * 2048];       // P fp16: cols 0-1023 logits,
                                                //         cols 1024-2047 window
__device__ __half g_A[(size_t)GM * GK];         // x fp16 (32 MiB)
__device__ __half g_Q[(size_t)GM * 1024];       // Q fp16
__device__ __half g_B1[2048 * GK];              // W_r^T fp16 [N][K]
__device__ __half g_B2[1024 * GK];              // W_w^T fp16 [N][K]

// ---------------------------------------------------------------------------
// PTX helpers (plain sm_103-legal only: cp.async / ldmatrix / mma.sync)
// ---------------------------------------------------------------------------
__device__ __forceinline__ uint32_t smem_to_u32(const void* p) {
    uint32_t a;
    asm("{ .reg .u64 t; cvta.to.shared.u64 t, %1; cvt.u32.u64 %0, t; }"
        : "=r"(a) : "l"(p));
    return a;
}

#define CP_ASYNC16(saddr, gptr) \
    asm volatile("cp.async.cg.shared.global [%0], [%1], 16;" \
                 :: "r"(saddr), "l"(gptr))
#define CP_COMMIT() asm volatile("cp.async.commit_group;" ::: "memory")
#define CP_WAIT(n)  asm volatile("cp.async.wait_group %0;" :: "n"(n) : "memory")

__device__ __forceinline__ void ldsm_x4(uint32_t (&r)[4], uint32_t addr) {
    asm volatile("ldmatrix.sync.aligned.m8n8.x4.shared.b16 {%0,%1,%2,%3}, [%4];"
                 : "=r"(r[0]), "=r"(r[1]), "=r"(r[2]), "=r"(r[3]) : "r"(addr));
}

// fp16-ACCUMULATOR mma: d(f16x2 x2) = a*b + c, c = constant zero pair.
// Hypothesis under test: f16-accum HMMA issues at full rate (8 cyc) vs the
// ~14-cyc effective interval measured for f32-accum across 7 experiments.
__device__ __forceinline__ void mma_f16h(uint32_t (&d)[2], const uint32_t (&a)[4],
                                         uint32_t b0, uint32_t b1, uint32_t zz) {
    asm volatile(
        "mma.sync.aligned.m16n8k16.row.col.f16.f16.f16.f16 "
        "{%0,%1}, {%2,%3,%4,%5}, {%6,%7}, {%8,%9};"
        : "=r"(d[0]), "=r"(d[1])
        : "r"(a[0]), "r"(a[1]), "r"(a[2]), "r"(a[3]), "r"(b0), "r"(b1),
          "r"(zz), "r"(zz));
}

// Promote one f16 d-frag (2 regs = 4 halfs) into 4 fp32 accumulators.
__device__ __forceinline__ void promote(float* a4, const uint32_t (&d)[2]) {
    float2 lo = __half22float2(*(const __half2*)&d[0]);
    float2 hi = __half22float2(*(const __half2*)&d[1]);
    a4[0] += lo.x; a4[1] += lo.y; a4[2] += hi.x; a4[3] += hi.y;
}

// SW128 swizzle for [rows][128 B] tiles.
__device__ __forceinline__ uint32_t tile_off128(int row, int kbyte) {
    return (uint32_t)(row * 128 + (kbyte ^ ((row & 7) << 4)));
}

// ---------------------------------------------------------------------------
// Fused prep kernel: block-range dispatch over three independent jobs.
// ---------------------------------------------------------------------------
__device__ __forceinline__ void transpose_body(
    const float* __restrict__ W, __half* __restrict__ Bh,
    int K, int N, int bx, int by, int tid, float (*t)[33])
{
    const int n0 = bx * 32, k0 = by * 32;
    const int tx = tid & 31, ty = tid >> 5;       // 32 x 8
    #pragma unroll
    for (int i = 0; i < 32; i += 8)
        t[ty + i][tx] = W[(size_t)(k0 + ty + i) * N + n0 + tx];
    __syncthreads();
    #pragma unroll
    for (int i = 0; i < 32; i += 8)
        Bh[(size_t)(n0 + ty + i) * K + (k0 + tx)] = __float2half_rn(t[tx][ty + i]);
}

#define PREP_RX_BLOCKS  (GM * GK / 4 / 256)          // 16384
#define PREP_T1_BLOCKS  ((2048 / 32) * (1024 / 32))  // 2048
#define PREP_T2_BLOCKS  ((1024 / 32) * (1024 / 32))  // 1024
#define PREP_GRID (PREP_RX_BLOCKS + PREP_T1_BLOCKS + PREP_T2_BLOCKS)

__global__ __launch_bounds__(256)
void prep_kernel(const float* __restrict__ X, __half* __restrict__ A,
                 const float* __restrict__ Wr, __half* __restrict__ B1,
                 const float* __restrict__ Ww, __half* __restrict__ B2)
{
    __shared__ float t[32][33];
    const int bid = blockIdx.x;
    const int tid = threadIdx.x;

    if (bid < PREP_RX_BLOCKS) {
        size_t i = (size_t)bid * 256 + tid;       // float4 idx
        float4 v = ((const float4*)X)[i];
        __half h[4];
        h[0] = __float2half_rn(v.x);
        h[1] = __float2half_rn(v.y);
        h[2] = __float2half_rn(v.z);
        h[3] = __float2half_rn(v.w);
        *(uint64_t*)(A + i * 4) = *(uint64_t*)h;
    } else if (bid < PREP_RX_BLOCKS + PREP_T1_BLOCKS) {
        int b2 = bid - PREP_RX_BLOCKS;
        transpose_body(Wr, B1, 1024, 2048, b2 & 63, b2 >> 6, tid, t);
    } else {
        int b2 = bid - PREP_RX_BLOCKS - PREP_T1_BLOCKS;
        transpose_body(Ww, B2, 1024, 1024, b2 & 31, b2 >> 5, tid, t);
    }
}

// ---------------------------------------------------------------------------
// fp16 GEMM via mma.sync with f16 accumulators + immediate fp32 promotion.
//   C = A @ B^T + bias.  One f16 rounding per 16-K segment (error ~2.2e-4).
// Output split: columns [0, nsplit) -> C32 fp32; [nsplit, N) -> C16 fp16.
// Tile 128x128xBK64, 3-stage cp.async pipeline, 256 threads
// (2m x 4n warps, warp tile 64x32), 2 CTAs/SM.
// ---------------------------------------------------------------------------
#define BKC 64
#define STAGE_BYTES 32768            // A 16KB + B 16KB
#define OFF_A 0
#define OFF_B 16384
#define NSTAGE 3
#define GEMM_SMEM (NSTAGE * STAGE_BYTES)   // 98304
#define NCHUNK (GK / BKC)                  // 16

__device__ __forceinline__ void issue_stage(uint32_t sbase,
    const __half* __restrict__ A, const __half* __restrict__ B,
    int k0, int tid)
{
    #pragma unroll
    for (int h = 0; h < 4; h++) {
        int idx = tid + h * 256;            // 0..1023
        int row = idx >> 3;                 // 0..127
        int kc  = idx & 7;                  // 16B chunk in 128B row
        uint32_t off = tile_off128(row, kc * 16);
        size_t g = (size_t)row * GK + k0 + kc * 8;
        CP_ASYNC16(sbase + OFF_A + off, A + g);
        CP_ASYNC16(sbase + OFF_B + off, B + g);
    }
}

__global__ __launch_bounds__(256, 2)
void gemm_mma_kernel(const __half* __restrict__ A,
                     const __half* __restrict__ B,
                     const float* __restrict__ bias,
                     float* __restrict__ C32,
                     __half* __restrict__ C16,
                     int N, int nsplit)
{
    extern __shared__ char smem[];
    const uint32_t sbase = smem_to_u32(smem);
    const int tid  = threadIdx.x;
    const int lane = tid & 31;
    const int wid  = tid >> 5;
    const int wm   = wid & 1;           // 0..1  (64-row half)
    const int wn   = wid >> 1;          // 0..3  (32-col quarter)
    const int m0 = blockIdx.y * 128;
    const int n0 = blockIdx.x * 128;

    const __half* Ab = A + (size_t)m0 * GK;
    const __half* Bb = B + (size_t)n0 * GK;

    const uint32_t zz = 0;              // constant zero c-frag

    float acc[4][4][4];
    #pragma unroll
    for (int i = 0; i < 4; i++)
        #pragma unroll
        for (int j = 0; j < 4; j++)
            #pragma unroll
            for (int q = 0; q < 4; q++) acc[i][j][q] = 0.f;

    // prologue: 2 stages in flight
    issue_stage(sbase + 0 * STAGE_BYTES, Ab, Bb, 0 * BKC, tid);
    CP_COMMIT();
    issue_stage(sbase + 1 * STAGE_BYTES, Ab, Bb, 1 * BKC, tid);
    CP_COMMIT();

    const int lrow = lane & 15;
    const int lcol = (lane >> 4) * 16;

    for (int c = 0; c < NCHUNK; c++) {
        if (c + 2 < NCHUNK) CP_WAIT(1); else CP_WAIT(0);
        __syncthreads();
        // Buffer (c+2)%3 was last read as chunk c-1; all warps passed the
        // barrier above only after finishing those reads.

        const uint32_t sb = sbase + (c % NSTAGE) * STAGE_BYTES;

        #pragma unroll
        for (int ks = 0; ks < 4; ks++) {
            const int kb = ks * 32 + lcol;
            uint32_t bf[2][4];
            #pragma unroll
            for (int ng = 0; ng < 2; ng++) {
                uint32_t o = tile_off128(wn * 32 + ng * 16 + lrow, kb);
                ldsm_x4(bf[ng], sb + OFF_B + o);
            }
            // Two m-halves: batch of 8 MMAs -> f16 d-frags -> promote to fp32.
            #pragma unroll
            for (int mh = 0; mh < 2; mh++) {
                uint32_t af[2][4];
                #pragma unroll
                for (int m2 = 0; m2 < 2; m2++) {
                    uint32_t o = tile_off128(wm * 64 + (mh * 2 + m2) * 16 + lrow, kb);
                    ldsm_x4(af[m2], sb + OFF_A + o);
                }
                uint32_t d[2][4][2];
                #pragma unroll
                for (int m2 = 0; m2 < 2; m2++)
                    #pragma unroll
                    for (int nt = 0; nt < 4; nt++)
                        mma_f16h(d[m2][nt], af[m2],
                                 bf[nt >> 1][nt & 1], bf[nt >> 1][(nt & 1) + 2], zz);
                #pragma unroll
                for (int m2 = 0; m2 < 2; m2++)
                    #pragma unroll
                    for (int nt = 0; nt < 4; nt++)
                        promote(acc[mh * 2 + m2][nt], d[m2][nt]);
            }

            if (ks == 0 && c + 2 < NCHUNK) {
                issue_stage(sbase + ((c + 2) % NSTAGE) * STAGE_BYTES,
                            Ab, Bb, (c + 2) * BKC, tid);
                CP_COMMIT();
            }
        }
    }

    // epilogue: fp32 columns < nsplit, fp16 columns >= nsplit
    if (n0 < nsplit) {
        float* Cblk = C32 + (size_t)m0 * nsplit + n0;
        #pragma unroll
        for (int mt = 0; mt < 4; mt++) {
            #pragma unroll
            for (int nt = 0; nt < 4; nt++) {
                int r  = wm * 64 + mt * 16 + (lane >> 2);
                int cc = wn * 32 + nt * 8 + (lane & 3) * 2;
                float b0 = __ldg(&bias[n0 + cc]);
                float b1 = __ldg(&bias[n0 + cc + 1]);
                float2 v0 = {acc[mt][nt][0] + b0, acc[mt][nt][1] + b1};
                float2 v1 = {acc[mt][nt][2] + b0, acc[mt][nt][3] + b1};
                *(float2*)(Cblk + (size_t)r * nsplit + cc) = v0;
                *(float2*)(Cblk + (size_t)(r + 8) * nsplit + cc) = v1;
            }
        }
    } else {
        const int w16 = N - nsplit;
        __half* Cblk = C16 + (size_t)m0 * w16 + (n0 - nsplit);
        #pragma unroll
        for (int mt = 0; mt < 4; mt++) {
            #pragma unroll
            for (int nt = 0; nt < 4; nt++) {
                int r  = wm * 64 + mt * 16 + (lane >> 2);
                int cc = wn * 32 + nt * 8 + (lane & 3) * 2;
                float b0 = __ldg(&bias[n0 + cc]);
                float b1 = __ldg(&bias[n0 + cc + 1]);
                __half2 h0 = __floats2half2_rn(acc[mt][nt][0] + b0,
                                               acc[mt][nt][1] + b1);
                __half2 h1 = __floats2half2_rn(acc[mt][nt][2] + b0,
                                               acc[mt][nt][3] + b1);
                *(__half2*)(Cblk + (size_t)r * w16 + cc) = h0;
                *(__half2*)(Cblk + (size_t)(r + 8) * w16 + cc) = h1;
            }
        }
    }
}

// ---------------------------------------------------------------------------
// Middle kernel v2 (unchanged from R15): one block per (chunk, batch),
// 512 threads = 16 t x 32 s-pairs, all-half2 I/O.
// ---------------------------------------------------------------------------
__global__ __launch_bounds__(512)
void middle_kernel(const __half* __restrict__ P,
                   __half* __restrict__ Q)
{
    __shared__ __half2 sR[30][16][32];   // [u][d][s-pair], rows 128B: no pad

    const int c  = blockIdx.x;
    const int b  = blockIdx.y;
    const int tid = threadIdx.x;
    const int sp = tid & 31;           // s-pair 0..31
    const int t  = tid >> 5;           // token-in-chunk 0..15

    const size_t base = (size_t)b * NTOK;

    for (int i = tid; i < 30 * 16 * 32; i += 512) {
        int spp = i & 31;
        int d   = (i >> 5) & 15;
        int u   = i >> 9;
        int tokn = c * DD + u + 1;
        if (tokn >= NTOK) tokn -= NTOK;
        sR[u][d][spp] = *(const __half2*)(
            P + (base + tokn) * 2048 + 1024 + d * 64 + spp * 2);
    }
    __syncthreads();

    const int n = c * DD + t;
    const __half2* p0 = (const __half2*)(P + (base + n) * 2048 + sp * 2);

    float2 v[16];
    float mx0 = -1e30f, mx1 = -1e30f;
    #pragma unroll
    for (int d = 0; d < 16; d++) {
        float2 f = __half22float2(p0[d * 32]);
        v[d] = f;
        mx0 = fmaxf(mx0, f.x);
        mx1 = fmaxf(mx1, f.y);
    }
    float s0 = 0.f, s1 = 0.f;
    #pragma unroll
    for (int d = 0; d < 16; d++) {
        v[d].x = __expf(v[d].x - mx0);
        v[d].y = __expf(v[d].y - mx1);
        s0 += v[d].x; s1 += v[d].y;
    }
    const float i0 = 1.f / s0, i1 = 1.f / s1;
    #pragma unroll
    for (int d = 0; d < 16; d++) { v[d].x *= i0; v[d].y *= i1; }

    __half2* qout = (__half2*)(Q + (base + n) * 1024 + sp * 2);
    const bool lastc = (c == NC - 1);

    #pragma unroll
    for (int d = 0; d < 16; d++) {
        float a0 = 0.f, a1 = 0.f;
        #pragma unroll
        for (int m = 0; m < d; m++) {
            float2 r = __half22float2(sR[t + m][d - 1 - m][sp]);
            a0 += v[m].x * r.x;
            a1 += v[m].y * r.y;
        }
        if (lastc && (t + d >= DD)) { a0 = 0.f; a1 = 0.f; }
        qout[d * 32] = __floats2half2_rn(a0, a1);
    }
}

// ---------------------------------------------------------------------------
extern "C" void kernel_launch(void* const* d_in, const int* in_sizes, int n_in,
                              void* d_out, int out_size)
{
    const float* x  = (const float*)d_in[0];   // [4,4096,1024]
    const float* Wr = (const float*)d_in[1];   // [1024,2048]
    const float* br = (const float*)d_in[2];   // [2048]
    const float* Ww = (const float*)d_in[3];   // [1024,1024]
    const float* bw = (const float*)d_in[4];   // [1024]
    float* out = (float*)d_out;                // [4,4096,1024]

    __half *P, *A, *Q, *B1, *B2;
    cudaGetSymbolAddress((void**)&P,  g_P);
    cudaGetSymbolAddress((void**)&A,  g_A);
    cudaGetSymbolAddress((void**)&Q,  g_Q);
    cudaGetSymbolAddress((void**)&B1, g_B1);
    cudaGetSymbolAddress((void**)&B2, g_B2);

    cudaFuncSetAttribute(gemm_mma_kernel,
                         cudaFuncAttributeMaxDynamicSharedMemorySize, GEMM_SMEM);

    // Fused prep: round x, transpose+round both weight matrices
    prep_kernel<<<PREP_GRID, 256>>>(x, A, Wr, B1, Ww, B2);

    // GEMM1: P = x @ W_r + b_r; ALL columns -> fp16 P (nsplit = 0)
    {
        dim3 grid(2048 / 128, GM / 128);
        gemm_mma_kernel<<<grid, 256, GEMM_SMEM>>>(A, B1, br, out, P, 2048, 0);
    }
    // Middle: softmax + triangular conv -> Q (fp16), one block per (c,b)
    {
        dim3 grid(NC, BB);
        middle_kernel<<<grid, 512>>>(P, Q);
    }
    // GEMM2: out = Q @ W_w + b_w; ALL columns -> fp32 (nsplit = N)
    {
        dim3 grid(1024 / 128, GM / 128);
        gemm_mma_kernel<<<grid, 256, GEMM_SMEM>>>(Q, B2, bw, out, (__half*)Q,
                                                  1024, 1024);
    }
}

// round 17
// speedup vs baseline: 1.3926x; 1.3926x over previous
#include <cuda_runtime.h>
#include <cuda_bf16.h>
#include <cuda_fp16.h>
#include <cstdint>

// R17 = R15 verbatim (measured optimum 350.3us, rel_err 5.08e-4).
// R16's f16-accumulator experiment is reverted: tensor-busy time was
// identical (f16-accum HMMA issues at the same rate as f32-accum on
// sm_103) and the fp32-promotion FFMAs flooded the issue slots (+39% fma
// pipe, 1.5x kernel time). GEMM duty ~60% is an intrinsic ceiling of the
// legacy mma.sync path here; tcgen05 is unreachable (harness targets
// plain sm_103 PTX).

// Problem constants
#define BB   4
#define NTOK 4096
#define PD   1024
#define DD   16
#define NC   (NTOK / DD)
#define GK   1024                 // K of both GEMMs
#define GM   (BB * NTOK)          // 16384 rows

// ---------------------------------------------------------------------------
// Scratch (device globals: allocation-free rule)
// ---------------------------------------------------------------------------
__device__ __half g_P[(size_t)GM * 2048];       // P fp16: cols 0-1023 logits,
                                                //         cols 1024-2047 window
__device__ __half g_A[(size_t)GM * GK];         // x fp16 (32 MiB)
__device__ __half g_Q[(size_t)GM * 1024];       // Q fp16
__device__ __half g_B1[2048 * GK];              // W_r^T fp16 [N][K]
__device__ __half g_B2[1024 * GK];              // W_w^T fp16 [N][K]

// ---------------------------------------------------------------------------
// PTX helpers (plain sm_103-legal only: cp.async / ldmatrix / mma.sync)
// ---------------------------------------------------------------------------
__device__ __forceinline__ uint32_t smem_to_u32(const void* p) {
    uint32_t a;
    asm("{ .reg .u64 t; cvta.to.shared.u64 t, %1; cvt.u32.u64 %0, t; }"
        : "=r"(a) : "l"(p));
    return a;
}

#define CP_ASYNC16(saddr, gptr) \
    asm volatile("cp.async.cg.shared.global [%0], [%1], 16;" \
                 :: "r"(saddr), "l"(gptr))
#define CP_COMMIT() asm volatile("cp.async.commit_group;" ::: "memory")
#define CP_WAIT(n)  asm volatile("cp.async.wait_group %0;" :: "n"(n) : "memory")

__device__ __forceinline__ void ldsm_x4(uint32_t (&r)[4], uint32_t addr) {
    asm volatile("ldmatrix.sync.aligned.m8n8.x4.shared.b16 {%0,%1,%2,%3}, [%4];"
                 : "=r"(r[0]), "=r"(r[1]), "=r"(r[2]), "=r"(r[3]) : "r"(addr));
}

__device__ __forceinline__ void mma_f16(float (&d)[4], const uint32_t (&a)[4],
                                        uint32_t b0, uint32_t b1) {
    asm volatile(
        "mma.sync.aligned.m16n8k16.row.col.f32.f16.f16.f32 "
        "{%0,%1,%2,%3}, {%4,%5,%6,%7}, {%8,%9}, {%0,%1,%2,%3};"
        : "+f"(d[0]), "+f"(d[1]), "+f"(d[2]), "+f"(d[3])
        : "r"(a[0]), "r"(a[1]), "r"(a[2]), "r"(a[3]), "r"(b0), "r"(b1));
}

// SW128 swizzle for [rows][128 B] tiles.
__device__ __forceinline__ uint32_t tile_off128(int row, int kbyte) {
    return (uint32_t)(row * 128 + (kbyte ^ ((row & 7) << 4)));
}

// ---------------------------------------------------------------------------
// Fused prep kernel: block-range dispatch over three independent jobs.
//   blocks [0, 16384)          : round x fp32 -> fp16            (g_A)
//   blocks [16384, 16384+2048) : transpose+round W_r -> B1 [N][K]
//   blocks [.., +1024)         : transpose+round W_w -> B2 [N][K]
// All blocks are 256 threads.
// ---------------------------------------------------------------------------
__device__ __forceinline__ void transpose_body(
    const float* __restrict__ W, __half* __restrict__ Bh,
    int K, int N, int bx, int by, int tid, float (*t)[33])
{
    const int n0 = bx * 32, k0 = by * 32;
    const int tx = tid & 31, ty = tid >> 5;       // 32 x 8
    #pragma unroll
    for (int i = 0; i < 32; i += 8)
        t[ty + i][tx] = W[(size_t)(k0 + ty + i) * N + n0 + tx];
    __syncthreads();
    #pragma unroll
    for (int i = 0; i < 32; i += 8)
        Bh[(size_t)(n0 + ty + i) * K + (k0 + tx)] = __float2half_rn(t[tx][ty + i]);
}

#define PREP_RX_BLOCKS  (GM * GK / 4 / 256)          // 16384
#define PREP_T1_BLOCKS  ((2048 / 32) * (1024 / 32))  // 2048
#define PREP_T2_BLOCKS  ((1024 / 32) * (1024 / 32))  // 1024
#define PREP_GRID (PREP_RX_BLOCKS + PREP_T1_BLOCKS + PREP_T2_BLOCKS)

__global__ __launch_bounds__(256)
void prep_kernel(const float* __restrict__ X, __half* __restrict__ A,
                 const float* __restrict__ Wr, __half* __restrict__ B1,
                 const float* __restrict__ Ww, __half* __restrict__ B2)
{
    __shared__ float t[32][33];
    const int bid = blockIdx.x;
    const int tid = threadIdx.x;

    if (bid < PREP_RX_BLOCKS) {
        size_t i = (size_t)bid * 256 + tid;       // float4 idx
        float4 v = ((const float4*)X)[i];
        __half h[4];
        h[0] = __float2half_rn(v.x);
        h[1] = __float2half_rn(v.y);
        h[2] = __float2half_rn(v.z);
        h[3] = __float2half_rn(v.w);
        *(uint64_t*)(A + i * 4) = *(uint64_t*)h;
    } else if (bid < PREP_RX_BLOCKS + PREP_T1_BLOCKS) {
        int b2 = bid - PREP_RX_BLOCKS;
        transpose_body(Wr, B1, 1024, 2048, b2 & 63, b2 >> 6, tid, t);
    } else {
        int b2 = bid - PREP_RX_BLOCKS - PREP_T1_BLOCKS;
        transpose_body(Ww, B2, 1024, 1024, b2 & 31, b2 >> 5, tid, t);
    }
}

// ---------------------------------------------------------------------------
// fp16 GEMM via mma.sync:  C = A @ B^T + bias   (single pass, fp32 accum)
//   A: [M][K] fp16 row-major;  B: [N][K] fp16 row-major
// Output split: columns [0, nsplit) -> C32 (fp32, row stride nsplit);
//               columns [nsplit, N) -> C16 (fp16, row stride N-nsplit).
// Tile 128x128xBK64, 3-stage cp.async pipeline, 256 threads
// (2m x 4n warps, warp tile 64x32), 2 CTAs/SM.  [FROZEN: duty ~60% pinned
// by the HMMA operand-path limit across 8 experiments incl. accum dtype.]
// ---------------------------------------------------------------------------
#define BKC 64
#define STAGE_BYTES 32768            // A 16KB + B 16KB
#define OFF_A 0
#define OFF_B 16384
#define NSTAGE 3
#define GEMM_SMEM (NSTAGE * STAGE_BYTES)   // 98304
#define NCHUNK (GK / BKC)                  // 16

__device__ __forceinline__ void issue_stage(uint32_t sbase,
    const __half* __restrict__ A, const __half* __restrict__ B,
    int k0, int tid)
{
    #pragma unroll
    for (int h = 0; h < 4; h++) {
        int idx = tid + h * 256;            // 0..1023
        int row = idx >> 3;                 // 0..127
        int kc  = idx & 7;                  // 16B chunk in 128B row
        uint32_t off = tile_off128(row, kc * 16);
        size_t g = (size_t)row * GK + k0 + kc * 8;
        CP_ASYNC16(sbase + OFF_A + off, A + g);
        CP_ASYNC16(sbase + OFF_B + off, B + g);
    }
}

__global__ __launch_bounds__(256, 2)
void gemm_mma_kernel(const __half* __restrict__ A,
                     const __half* __restrict__ B,
                     const float* __restrict__ bias,
                     float* __restrict__ C32,
                     __half* __restrict__ C16,
                     int N, int nsplit)
{
    extern __shared__ char smem[];
    const uint32_t sbase = smem_to_u32(smem);
    const int tid  = threadIdx.x;
    const int lane = tid & 31;
    const int wid  = tid >> 5;
    const int wm   = wid & 1;           // 0..1  (64-row half)
    const int wn   = wid >> 1;          // 0..3  (32-col quarter)
    const int m0 = blockIdx.y * 128;
    const int n0 = blockIdx.x * 128;

    const __half* Ab = A + (size_t)m0 * GK;
    const __half* Bb = B + (size_t)n0 * GK;

    float acc[4][4][4];
    #pragma unroll
    for (int i = 0; i < 4; i++)
        #pragma unroll
        for (int j = 0; j < 4; j++)
            #pragma unroll
            for (int q = 0; q < 4; q++) acc[i][j][q] = 0.f;

    // prologue: 2 stages in flight
    issue_stage(sbase + 0 * STAGE_BYTES, Ab, Bb, 0 * BKC, tid);
    CP_COMMIT();
    issue_stage(sbase + 1 * STAGE_BYTES, Ab, Bb, 1 * BKC, tid);
    CP_COMMIT();

    const int lrow = lane & 15;
    const int lcol = (lane >> 4) * 16;

    for (int c = 0; c < NCHUNK; c++) {
        if (c + 2 < NCHUNK) CP_WAIT(1); else CP_WAIT(0);
        __syncthreads();
        // Buffer (c+2)%3 was last read as chunk c-1; all warps passed the
        // barrier above only after finishing those reads.

        const uint32_t sb = sbase + (c % NSTAGE) * STAGE_BYTES;

        #pragma unroll
        for (int ks = 0; ks < 4; ks++) {
            const int kb = ks * 32 + lcol;
            uint32_t af[4][4];
            #pragma unroll
            for (int mt = 0; mt < 4; mt++) {
                uint32_t o = tile_off128(wm * 64 + mt * 16 + lrow, kb);
                ldsm_x4(af[mt], sb + OFF_A + o);
            }
            uint32_t bf[2][4];
            #pragma unroll
            for (int ng = 0; ng < 2; ng++) {
                uint32_t o = tile_off128(wn * 32 + ng * 16 + lrow, kb);
                ldsm_x4(bf[ng], sb + OFF_B + o);
            }
            #pragma unroll
            for (int mt = 0; mt < 4; mt++)
                #pragma unroll
                for (int nt = 0; nt < 4; nt++)
                    mma_f16(acc[mt][nt], af[mt],
                            bf[nt >> 1][nt & 1], bf[nt >> 1][(nt & 1) + 2]);

            if (ks == 0 && c + 2 < NCHUNK) {
                issue_stage(sbase + ((c + 2) % NSTAGE) * STAGE_BYTES,
                            Ab, Bb, (c + 2) * BKC, tid);
                CP_COMMIT();
            }
        }
    }

    // epilogue: fp32 columns < nsplit, fp16 columns >= nsplit
    if (n0 < nsplit) {
        float* Cblk = C32 + (size_t)m0 * nsplit + n0;
        #pragma unroll
        for (int mt = 0; mt < 4; mt++) {
            #pragma unroll
            for (int nt = 0; nt < 4; nt++) {
                int r  = wm * 64 + mt * 16 + (lane >> 2);
                int cc = wn * 32 + nt * 8 + (lane & 3) * 2;
                float b0 = __ldg(&bias[n0 + cc]);
                float b1 = __ldg(&bias[n0 + cc + 1]);
                float2 v0 = {acc[mt][nt][0] + b0, acc[mt][nt][1] + b1};
                float2 v1 = {acc[mt][nt][2] + b0, acc[mt][nt][3] + b1};
                *(float2*)(Cblk + (size_t)r * nsplit + cc) = v0;
                *(float2*)(Cblk + (size_t)(r + 8) * nsplit + cc) = v1;
            }
        }
    } else {
        const int w16 = N - nsplit;
        __half* Cblk = C16 + (size_t)m0 * w16 + (n0 - nsplit);
        #pragma unroll
        for (int mt = 0; mt < 4; mt++) {
            #pragma unroll
            for (int nt = 0; nt < 4; nt++) {
                int r  = wm * 64 + mt * 16 + (lane >> 2);
                int cc = wn * 32 + nt * 8 + (lane & 3) * 2;
                float b0 = __ldg(&bias[n0 + cc]);
                float b1 = __ldg(&bias[n0 + cc + 1]);
                __half2 h0 = __floats2half2_rn(acc[mt][nt][0] + b0,
                                               acc[mt][nt][1] + b1);
                __half2 h1 = __floats2half2_rn(acc[mt][nt][2] + b0,
                                               acc[mt][nt][3] + b1);
                *(__half2*)(Cblk + (size_t)r * w16 + cc) = h0;
                *(__half2*)(Cblk + (size_t)(r + 8) * w16 + cc) = h1;
            }
        }
    }
}

// ---------------------------------------------------------------------------
// Middle kernel v2: one block per (chunk, batch), 512 threads = 16 t x 32
// s-pairs, all-half2 I/O. Window staged ONCE per (c,b), every global access
// a coalesced 128B/warp half2 transaction. fp32 softmax + conv.
//   p[n,m,s]  = softmax_m( P[b,n,m,s] )            (cols 0-1023)
//   Qg[n,d,s] = sum_{m<d} p[n,m,s] * P[(n+m+1)%N, 1024+(d-1-m)*64+s]
//   masked last chunk.
// ---------------------------------------------------------------------------
__global__ __launch_bounds__(512)
void middle_kernel(const __half* __restrict__ P,
                   __half* __restrict__ Q)
{
    __shared__ __half2 sR[30][16][32];   // [u][d][s-pair], rows 128B: no pad

    const int c  = blockIdx.x;
    const int b  = blockIdx.y;
    const int tid = threadIdx.x;
    const int sp = tid & 31;           // s-pair 0..31 (s = 2*sp, 2*sp+1)
    const int t  = tid >> 5;           // token-in-chunk 0..15

    const size_t base = (size_t)b * NTOK;

    // Stage window: 30 tokens x 16 d x 32 s-pairs, coalesced half2 loads
    for (int i = tid; i < 30 * 16 * 32; i += 512) {
        int spp = i & 31;
        int d   = (i >> 5) & 15;
        int u   = i >> 9;
        int tokn = c * DD + u + 1;
        if (tokn >= NTOK) tokn -= NTOK;
        sR[u][d][spp] = *(const __half2*)(
            P + (base + tokn) * 2048 + 1024 + d * 64 + spp * 2);
    }
    __syncthreads();

    const int n = c * DD + t;
    const __half2* p0 = (const __half2*)(P + (base + n) * 2048 + sp * 2);

    // softmax over 16 logits, two s-lanes at once (fp32 internally)
    float2 v[16];
    float mx0 = -1e30f, mx1 = -1e30f;
    #pragma unroll
    for (int d = 0; d < 16; d++) {
        float2 f = __half22float2(p0[d * 32]);   // stride 64 halfs = 32 half2
        v[d] = f;
        mx0 = fmaxf(mx0, f.x);
        mx1 = fmaxf(mx1, f.y);
    }
    float s0 = 0.f, s1 = 0.f;
    #pragma unroll
    for (int d = 0; d < 16; d++) {
        v[d].x = __expf(v[d].x - mx0);
        v[d].y = __expf(v[d].y - mx1);
        s0 += v[d].x; s1 += v[d].y;
    }
    const float i0 = 1.f / s0, i1 = 1.f / s1;
    #pragma unroll
    for (int d = 0; d < 16; d++) { v[d].x *= i0; v[d].y *= i1; }

    __half2* qout = (__half2*)(Q + (base + n) * 1024 + sp * 2);
    const bool lastc = (c == NC - 1);

    #pragma unroll
    for (int d = 0; d < 16; d++) {
        float a0 = 0.f, a1 = 0.f;
        #pragma unroll
        for (int m = 0; m < d; m++) {
            float2 r = __half22float2(sR[t + m][d - 1 - m][sp]);
            a0 += v[m].x * r.x;
            a1 += v[m].y * r.y;
        }
        if (lastc && (t + d >= DD)) { a0 = 0.f; a1 = 0.f; }
        qout[d * 32] = __floats2half2_rn(a0, a1);
    }
}

// ---------------------------------------------------------------------------
extern "C" void kernel_launch(void* const* d_in, const int* in_sizes, int n_in,
                              void* d_out, int out_size)
{
    const float* x  = (const float*)d_in[0];   // [4,4096,1024]
    const float* Wr = (const float*)d_in[1];   // [1024,2048]
    const float* br = (const float*)d_in[2];   // [2048]
    const float* Ww = (const float*)d_in[3];   // [1024,1024]
    const float* bw = (const float*)d_in[4];   // [1024]
    float* out = (float*)d_out;                // [4,4096,1024]

    __half *P, *A, *Q, *B1, *B2;
    cudaGetSymbolAddress((void**)&P,  g_P);
    cudaGetSymbolAddress((void**)&A,  g_A);
    cudaGetSymbolAddress((void**)&Q,  g_Q);
    cudaGetSymbolAddress((void**)&B1, g_B1);
    cudaGetSymbolAddress((void**)&B2, g_B2);

    cudaFuncSetAttribute(gemm_mma_kernel,
                         cudaFuncAttributeMaxDynamicSharedMemorySize, GEMM_SMEM);

    // Fused prep: round x, transpose+round both weight matrices
    prep_kernel<<<PREP_GRID, 256>>>(x, A, Wr, B1, Ww, B2);

    // GEMM1: P = x @ W_r + b_r; ALL columns -> fp16 P (nsplit = 0)
    {
        dim3 grid(2048 / 128, GM / 128);
        gemm_mma_kernel<<<grid, 256, GEMM_SMEM>>>(A, B1, br, out, P, 2048, 0);
    }
    // Middle: softmax + triangular conv -> Q (fp16), one block per (c,b)
    {
        dim3 grid(NC, BB);
        middle_kernel<<<grid, 512>>>(P, Q);
    }
    // GEMM2: out = Q @ W_w + b_w; ALL columns -> fp32 (nsplit = N)
    {
        dim3 grid(1024 / 128, GM / 128);
        gemm_mma_kernel<<<grid, 256, GEMM_SMEM>>>(Q, B2, bw, out, (__half*)Q,
                                                  1024, 1024);
    }
}